// round 6
// baseline (speedup 1.0000x reference)
#include <cuda_runtime.h>
#include <cuda_bf16.h>
#include <math.h>

// ---------------- constants ----------------
#define BB   32
#define LL   1024
#define DD   512
#define NH   8
#define HE   64
#define DFF  2048
#define CIN  7
#define MK   4
#define MROWS (BB*LL)          // 32768
#define BLD  (BB*LL*DD)        // 16777216
#define BL7  (BB*LL*CIN)       // 229376
#define TOPK 6

typedef __nv_bfloat16 bf16;

// ---------------- device scratch ----------------
__device__ float g_A   [BLD];
__device__ float g_Bf  [BLD];
__device__ float g_q   [BLD];
__device__ float g_k   [BLD];
__device__ float g_v   [BLD];
__device__ float g_enc [BLD];
__device__ float g_t123[BLD];
__device__ float g_qt  [BLD];
__device__ float g_kt  [BLD];
__device__ float2 g_Sp [BB*NH*4*LL];
__device__ float g_cm  [BB*DD];
__device__ float g_w   [BB*8];
__device__ int   g_dly [BB*8];
__device__ float g_sx  [BL7];
__device__ float g_tx  [BL7];
__device__ float g_seas[BL7];
__device__ float g_trd [BL7];
__device__ float g_menc[BB*CIN];
// bf16 split buffers
__device__ bf16 g_s1h[MROWS*DD];
__device__ bf16 g_s1l[MROWS*DD];
__device__ bf16 g_ench[MROWS*DD];
__device__ bf16 g_encl[MROWS*DD];
__device__ bf16 g_s2h[MROWS*DFF];
__device__ bf16 g_s2l[MROWS*DFF];
__device__ bf16 g_wbh[DFF*DD];
__device__ bf16 g_wbl[DFF*DD];

// ---------------- helpers ----------------
__device__ __forceinline__ void bsplit(float x, bf16& h, bf16& l){
    h = __float2bfloat16(x);
    l = __float2bfloat16(x - __bfloat162float(h));
}
__device__ __forceinline__ unsigned su32(const void* p){
    return (unsigned)__cvta_generic_to_shared(p);
}
__device__ __forceinline__ void cpa16(unsigned dst, const void* src){
    asm volatile("cp.async.cg.shared.global [%0], [%1], 16;" :: "r"(dst), "l"(src));
}
__device__ __forceinline__ void cpa_commit(){
    asm volatile("cp.async.commit_group;" ::: "memory");
}
__device__ __forceinline__ void cpa_wait2(){
    asm volatile("cp.async.wait_group 2;" ::: "memory");
}
__device__ __forceinline__ void ldsm4(unsigned* r, unsigned addr){
    asm volatile("ldmatrix.sync.aligned.m8n8.x4.shared.b16 {%0,%1,%2,%3}, [%4];"
        : "=r"(r[0]), "=r"(r[1]), "=r"(r[2]), "=r"(r[3]) : "r"(addr));
}
__device__ __forceinline__ void mma16(float* d, const unsigned* a, unsigned b0, unsigned b1){
    asm volatile("mma.sync.aligned.m16n8k16.row.col.f32.bf16.bf16.f32 "
        "{%0,%1,%2,%3},{%4,%5,%6,%7},{%8,%9},{%0,%1,%2,%3};"
        : "+f"(d[0]), "+f"(d[1]), "+f"(d[2]), "+f"(d[3])
        : "r"(a[0]), "r"(a[1]), "r"(a[2]), "r"(a[3]), "r"(b0), "r"(b1));
}

// ---------------- split-bf16 mma.sync GEMM ----------------
// C(M x N) = (Ah+Al)(Bh+Bl)^T; A: MxK bf16 k-major; B: NxK bf16 k-major.
// 128(M) x 256(N) CTA tile, 512 thr (16 warps, warp tile 32x64), KT=32, 3-stage cp.async.
#define RSTRIDE 80            // bytes per smem row (32 bf16 + 8 pad)
#define A_AREA  10240         // 128 rows * 80B
#define B_AREA  20480         // 256 rows * 80B
#define OFF_AL  10240
#define OFF_BH  20480
#define OFF_BL  40960
#define STAGEB  61440
#define GEMM_SMEM (3*STAGEB)  // 184320
__global__ void __launch_bounds__(512,1) gemm_mma_k(
    const bf16* __restrict__ Ahp, const bf16* __restrict__ Alp,
    const bf16* __restrict__ Bhp, const bf16* __restrict__ Blp,
    const float* __restrict__ bias, const float* __restrict__ res,
    float* __restrict__ C, bf16* __restrict__ Ch, bf16* __restrict__ Cl,
    int N, int K, int dogelu)
{
    extern __shared__ __align__(16) char dsm[];
    const int tid = threadIdx.x;
    const int lane = tid & 31, warp = tid >> 5;
    const int wm = warp & 3, wn = warp >> 2;
    const int bx = blockIdx.x, by = blockIdx.y;
    const int S = K >> 5;
    const unsigned sbase = su32(dsm);

    // producer mapping
    const int arow = tid >> 2, ac = tid & 3;          // A: 128 rows x 4 chunks
    const int brow = tid >> 1, bc = (tid & 1) << 1;   // B: 256 rows x (2 chunks each)
    const bf16* gA_h = Ahp + (size_t)(by*128 + arow)*K + ac*8;
    const bf16* gA_l = Alp + (size_t)(by*128 + arow)*K + ac*8;
    const bf16* gB_h = Bhp + (size_t)(bx*256 + brow)*K + bc*8;
    const bf16* gB_l = Blp + (size_t)(bx*256 + brow)*K + bc*8;
    const unsigned sdA = arow*RSTRIDE + ac*16;
    const unsigned sdB = brow*RSTRIDE + bc*16;

    float acc[2][2][4][4];   // [mf][nh][nf][4]
#pragma unroll
    for (int i=0;i<2;i++)
#pragma unroll
        for (int j=0;j<2;j++)
#pragma unroll
            for (int n=0;n<4;n++)
#pragma unroll
                for (int t=0;t<4;t++) acc[i][j][n][t]=0.f;

#pragma unroll
    for (int p=0;p<3;p++){
        if (p < S){
            unsigned sb = sbase + p*STAGEB;
            int gk = p*32;
            cpa16(sb + sdA,                  gA_h + gk);
            cpa16(sb + OFF_AL + sdA,         gA_l + gk);
            cpa16(sb + OFF_BH + sdB,         gB_h + gk);
            cpa16(sb + OFF_BH + sdB + 16,    gB_h + gk + 8);
            cpa16(sb + OFF_BL + sdB,         gB_l + gk);
            cpa16(sb + OFF_BL + sdB + 16,    gB_l + gk + 8);
        }
        cpa_commit();
    }

    const unsigned aoff = (wm*32 + (lane & 15))*RSTRIDE + (lane >> 4)*16;
    const unsigned boff = (wn*64 + (lane & 15))*RSTRIDE + (lane >> 4)*16;

    for (int s=0; s<S; s++){
        cpa_wait2();
        __syncthreads();
        const unsigned sb = sbase + (s % 3)*STAGEB;
#pragma unroll
        for (int k16=0; k16<2; k16++){
            const unsigned ko = k16*32;
            unsigned ah[8], al[8];
            ldsm4(ah,   sb + aoff + ko);
            ldsm4(ah+4, sb + aoff + ko + 16*RSTRIDE);
            ldsm4(al,   sb + OFF_AL + aoff + ko);
            ldsm4(al+4, sb + OFF_AL + aoff + ko + 16*RSTRIDE);
#pragma unroll
            for (int nh=0; nh<2; nh++){
                const unsigned bo = boff + nh*(32*RSTRIDE) + ko;
                unsigned bh[8], bl[8];
                ldsm4(bh,   sb + OFF_BH + bo);
                ldsm4(bh+4, sb + OFF_BH + bo + 16*RSTRIDE);
                ldsm4(bl,   sb + OFF_BL + bo);
                ldsm4(bl+4, sb + OFF_BL + bo + 16*RSTRIDE);
                // term-major ordering: same-acc reuse distance = 8 mmas
#pragma unroll
                for (int mf=0; mf<2; mf++)
#pragma unroll
                    for (int nf=0; nf<4; nf++){
                        int g = (nf>>1)*4 + (nf&1);
                        mma16(acc[mf][nh][nf], ah+mf*4, bh[g], bh[g+2]);
                    }
#pragma unroll
                for (int mf=0; mf<2; mf++)
#pragma unroll
                    for (int nf=0; nf<4; nf++){
                        int g = (nf>>1)*4 + (nf&1);
                        mma16(acc[mf][nh][nf], ah+mf*4, bl[g], bl[g+2]);
                    }
#pragma unroll
                for (int mf=0; mf<2; mf++)
#pragma unroll
                    for (int nf=0; nf<4; nf++){
                        int g = (nf>>1)*4 + (nf&1);
                        mma16(acc[mf][nh][nf], al+mf*4, bh[g], bh[g+2]);
                    }
            }
        }
        __syncthreads();
        if (s+3 < S){
            unsigned sb2 = sbase + (s % 3)*STAGEB;
            int gk = (s+3)*32;
            cpa16(sb2 + sdA,                  gA_h + gk);
            cpa16(sb2 + OFF_AL + sdA,         gA_l + gk);
            cpa16(sb2 + OFF_BH + sdB,         gB_h + gk);
            cpa16(sb2 + OFF_BH + sdB + 16,    gB_h + gk + 8);
            cpa16(sb2 + OFF_BL + sdB,         gB_l + gk);
            cpa16(sb2 + OFF_BL + sdB + 16,    gB_l + gk + 8);
        }
        cpa_commit();
    }

    // epilogue
#pragma unroll
    for (int mf=0; mf<2; mf++){
#pragma unroll
        for (int nh=0; nh<2; nh++){
#pragma unroll
            for (int nf=0; nf<4; nf++){
                int r0  = by*128 + wm*32 + mf*16 + (lane>>2);
                int col = bx*256 + wn*64 + nh*32 + nf*8 + ((lane&3)<<1);
                float* d = acc[mf][nh][nf];
#pragma unroll
                for (int h=0; h<2; h++){
                    int r = r0 + h*8;
                    size_t rowoff = (size_t)r * N;
                    float2 o = make_float2(d[2*h], d[2*h+1]);
                    if (bias){ o.x += __ldg(&bias[col]); o.y += __ldg(&bias[col+1]); }
                    if (dogelu){
                        o.x = 0.5f*o.x*(1.0f+erff(o.x*0.7071067811865476f));
                        o.y = 0.5f*o.y*(1.0f+erff(o.y*0.7071067811865476f));
                    }
                    if (res){
                        float2 rr = *(const float2*)&res[rowoff + col];
                        o.x += rr.x; o.y += rr.y;
                    }
                    if (Ch){
                        bf16 h0,l0,h1,l1;
                        bsplit(o.x,h0,l0); bsplit(o.y,h1,l1);
                        __nv_bfloat162 hv; hv.x=h0; hv.y=h1;
                        __nv_bfloat162 lv; lv.x=l0; lv.y=l1;
                        *(__nv_bfloat162*)&Ch[rowoff + col] = hv;
                        *(__nv_bfloat162*)&Cl[rowoff + col] = lv;
                    } else {
                        *(float2*)&C[rowoff + col] = o;
                    }
                }
            }
        }
    }
}

// ---------------- weight split + transpose: W[Kd x Nd] -> out[Nd x Kd] hi/lo ----------------
__global__ void split_tr_k(const float* __restrict__ W, bf16* __restrict__ oh,
                           bf16* __restrict__ ol, int Kd, int Nd){
    __shared__ float t[32][33];
    int n0 = blockIdx.x*32, k0 = blockIdx.y*32;
    int x = threadIdx.x, y = threadIdx.y;
    for (int i=y;i<32;i+=8)
        t[i][x] = W[(size_t)(k0+i)*Nd + n0 + x];
    __syncthreads();
    for (int i=y;i<32;i+=8){
        float v = t[x][i];
        bf16 h,l; bsplit(v,h,l);
        oh[(size_t)(n0+i)*Kd + k0 + x] = h;
        ol[(size_t)(n0+i)*Kd + k0 + x] = l;
    }
}

// ---------------- transpose (B,1024,512) -> (B,512,1024) ----------------
__global__ void transpose_k(const float* __restrict__ in, float* __restrict__ out){
    __shared__ float tile[32][33];
    int b = blockIdx.z;
    int t0 = blockIdx.x*32, c0 = blockIdx.y*32;
    int x = threadIdx.x, y = threadIdx.y;
    for (int i=y;i<32;i+=8)
        tile[i][x] = in[((size_t)b*LL + t0+i)*DD + c0 + x];
    __syncthreads();
    for (int i=y;i<32;i+=8)
        out[((size_t)b*DD + c0+i)*LL + t0 + x] = tile[x][i];
}

// ---------------- FFT helpers ----------------
__device__ __forceinline__ float2 cmul(float2 a, float2 b){
    return make_float2(a.x*b.x - a.y*b.y, a.x*b.y + a.y*b.x);
}
__device__ void fft1024(float2* z, const float2* tw, int tid){
#pragma unroll
    for (int s=0;s<10;s++){
        __syncthreads();
        int half = 1 << s;
#pragma unroll
        for (int r=0;r<2;r++){
            int j = tid + r*256;
            int pos = j & (half-1);
            int grp = j >> s;
            int i0 = (grp << (s+1)) + pos;
            int i1 = i0 + half;
            float2 w = tw[pos << (9 - s)];
            float2 a = z[i0], b = z[i1];
            float2 t = cmul(w, b);
            z[i0] = make_float2(a.x+t.x, a.y+t.y);
            z[i1] = make_float2(a.x-t.x, a.y-t.y);
        }
    }
    __syncthreads();
}

#define EPB 16
__global__ void corr_fwd_k(const float* __restrict__ qt, const float* __restrict__ kt,
                           float2* __restrict__ Sp){
    __shared__ float2 z[1024];
    __shared__ float2 acc[1024];
    __shared__ float2 tw[512];
    int bh = blockIdx.x;
    int chunk = blockIdx.y;
    int tid = threadIdx.x;
    for (int j=tid;j<512;j+=256){
        float s,c; sincosf((float)j * (6.283185307179586f/1024.0f), &s, &c);
        tw[j] = make_float2(c, -s);
    }
    for (int f=tid;f<1024;f+=256) acc[f] = make_float2(0.f,0.f);
    for (int ei=0; ei<EPB; ei++){
        int e = chunk*EPB + ei;
        const float* qp = qt + ((size_t)bh*HE + e)*LL;
        const float* kp = kt + ((size_t)bh*HE + e)*LL;
        __syncthreads();
        for (int t=tid;t<1024;t+=256){
            int r = __brev(t) >> 22;
            z[r] = make_float2(qp[t], kp[t]);
        }
        fft1024(z, tw, tid);
        for (int f=tid;f<1024;f+=256){
            float2 Zf = z[f];
            float2 Zm = z[(1024 - f) & 1023];
            float2 Zc = make_float2(Zm.x, -Zm.y);
            float2 Q  = make_float2(0.5f*(Zf.x+Zc.x), 0.5f*(Zf.y+Zc.y));
            float dx = Zf.x - Zc.x, dy = Zf.y - Zc.y;
            float2 Kk = make_float2(0.5f*dy, -0.5f*dx);
            acc[f].x += Q.x*Kk.x + Q.y*Kk.y;
            acc[f].y += Q.y*Kk.x - Q.x*Kk.y;
        }
    }
    __syncthreads();
    float2* dst = Sp + ((size_t)bh*4 + chunk)*LL;
    for (int f=tid;f<1024;f+=256) dst[f] = acc[f];
}

__global__ void corr_topk_k(const float2* __restrict__ Sp, float* __restrict__ wout,
                            int* __restrict__ dout){
    __shared__ float2 z[1024];
    __shared__ float2 tw[512];
    __shared__ float corr[1024];
    __shared__ float rv[256];
    __shared__ int   ri[256];
    __shared__ float wv[TOPK];
    __shared__ int   dv[TOPK];
    int b = blockIdx.x, tid = threadIdx.x;
    for (int j=tid;j<512;j+=256){
        float s,c; sincosf((float)j * (6.283185307179586f/1024.0f), &s, &c);
        tw[j] = make_float2(c, s);
    }
    for (int f=tid;f<1024;f+=256){
        float sx=0.f, sy=0.f;
        const float2* sp = Sp + (size_t)b*32*LL + f;
#pragma unroll
        for (int sl=0;sl<32;sl++){
            float2 v = sp[(size_t)sl*LL];
            sx += v.x; sy += v.y;
        }
        int r = __brev(f) >> 22;
        z[r] = make_float2(sx, sy);
    }
    fft1024(z, tw, tid);
    const float scale = 1.0f / (1024.0f * 512.0f);
    for (int f=tid;f<1024;f+=256) corr[f] = z[f].x * scale;
    __syncthreads();
    for (int it=0; it<TOPK; it++){
        float best = -1e30f; int bi = 1<<30;
        for (int f=tid;f<1024;f+=256){
            float v = corr[f];
            if (v > best || (v == best && f < bi)){ best = v; bi = f; }
        }
        rv[tid]=best; ri[tid]=bi; __syncthreads();
        for (int off=128; off; off>>=1){
            if (tid < off){
                if (rv[tid+off] > rv[tid] || (rv[tid+off]==rv[tid] && ri[tid+off]<ri[tid])){
                    rv[tid]=rv[tid+off]; ri[tid]=ri[tid+off];
                }
            }
            __syncthreads();
        }
        if (tid==0){ wv[it]=rv[0]; dv[it]=ri[0]; corr[ri[0]] = -1e30f; }
        __syncthreads();
    }
    if (tid==0){
        float mx = wv[0];
        float ex[TOPK]; float s=0.f;
        for (int i=0;i<TOPK;i++){ ex[i]=expf(wv[i]-mx); s+=ex[i]; }
        for (int i=0;i<TOPK;i++){ wout[b*8+i]=ex[i]/s; dout[b*8+i]=dv[i]; }
    }
}

// ---------------- roll & weight -> bf16 splits ----------------
__global__ void roll_split_k(const float* __restrict__ V, const float* __restrict__ w,
                             const int* __restrict__ d, bf16* __restrict__ oh,
                             bf16* __restrict__ ol){
    int idx = blockIdx.x*256 + threadIdx.x;
    if (idx >= BLD) return;
    int c = idx & (DD-1);
    int t = (idx >> 9) & (LL-1);
    int b = idx >> 19;
    float s = 0.f;
#pragma unroll
    for (int i=0;i<TOPK;i++){
        int   dl = __ldg(&d[b*8+i]);
        float wi = __ldg(&w[b*8+i]);
        int tt = (t + dl) & (LL-1);
        s += wi * __ldg(&V[((size_t)b*LL + tt)*DD + c]);
    }
    bf16 h,l; bsplit(s,h,l);
    oh[idx]=h; ol[idx]=l;
}

// ---------------- series decomposition (moving mean k=25) ----------------
__global__ void decomp_k(const float* __restrict__ x, float* __restrict__ seas,
                         float* __restrict__ trend, int C, int mode,
                         bf16* __restrict__ oh, bf16* __restrict__ ol){
    int b = blockIdx.z;
    int c = blockIdx.x*blockDim.x + threadIdx.x;
    if (c >= C) return;
    int l0 = blockIdx.y * 128;
    const float* xb = x + (size_t)b*LL*C + c;
    float sum = 0.f;
    for (int j=l0-12;j<=l0+12;j++){
        int jj = min(max(j,0), LL-1);
        sum += xb[(size_t)jj*C];
    }
    for (int l=l0; l<l0+128; l++){
        float m = sum * (1.0f/25.0f);
        size_t o = (size_t)b*LL*C + (size_t)l*C + c;
        float sv = x[o] - m;
        seas[o] = sv;
        if (oh){ bf16 h,lo; bsplit(sv,h,lo); oh[o]=h; ol[o]=lo; }
        if (mode==1) trend[o] = m;
        else if (mode==2) trend[o] += m;
        int ja = min(l+13, LL-1), jr = max(l-12, 0);
        sum += xb[(size_t)ja*C] - xb[(size_t)jr*C];
    }
}

// ---------------- layernorm over feature dim ----------------
__global__ void ln_k(const float* __restrict__ x, const float* __restrict__ w,
                     const float* __restrict__ bv, float* __restrict__ y){
    __shared__ float red[256];
    int row = blockIdx.x, tid = threadIdx.x;
    const float* xr = x + (size_t)row*DD;
    float v0 = xr[tid], v1 = xr[tid+256];
    red[tid] = v0+v1; __syncthreads();
    for (int o=128;o;o>>=1){ if (tid<o) red[tid]+=red[tid+o]; __syncthreads(); }
    float mu = red[0]*(1.0f/512.0f);
    __syncthreads();
    float d0=v0-mu, d1=v1-mu;
    red[tid] = d0*d0+d1*d1; __syncthreads();
    for (int o=128;o;o>>=1){ if (tid<o) red[tid]+=red[tid+o]; __syncthreads(); }
    float rstd = rsqrtf(red[0]*(1.0f/512.0f) + 1e-5f);
    y[(size_t)row*DD + tid]     = d0*rstd*w[tid]     + bv[tid];
    y[(size_t)row*DD + tid+256] = d1*rstd*w[tid+256] + bv[tid+256];
}

// ---------------- column (time) mean ----------------
__global__ void zero_k(float* p, int n){
    int i = blockIdx.x*blockDim.x + threadIdx.x;
    if (i < n) p[i] = 0.0f;
}
__global__ void colsum_k(const float* __restrict__ x, float* __restrict__ cm){
    int b = blockIdx.z;
    int c = blockIdx.x*256 + threadIdx.x;
    int l0 = blockIdx.y*128;
    float s=0.f;
    for (int l=l0;l<l0+128;l++) s += x[((size_t)b*LL + l)*DD + c];
    atomicAdd(&cm[b*DD + c], s);
}
__global__ void colsub_k(const float* __restrict__ x, const float* __restrict__ cm,
                         float* __restrict__ y, bf16* __restrict__ oh, bf16* __restrict__ ol){
    int idx = blockIdx.x*256 + threadIdx.x;
    if (idx >= BLD) return;
    int c = idx & (DD-1);
    int b = idx >> 19;
    float v = x[idx] - cm[b*DD + c]*(1.0f/1024.0f);
    y[idx] = v;
    if (oh){ bf16 h,l; bsplit(v,h,l); oh[idx]=h; ol[idx]=l; }
}

// ---------------- embedding ----------------
__global__ void embed_k(const float* __restrict__ x, const float* __restrict__ mark,
                        const float* __restrict__ Wtok, const float* __restrict__ Wtem,
                        float* __restrict__ out, bf16* __restrict__ oh, bf16* __restrict__ ol){
    int idx = blockIdx.x*256 + threadIdx.x;
    if (idx >= BLD) return;
    int d = idx & (DD-1);
    int l = (idx >> 9) & (LL-1);
    int b = idx >> 19;
    int lm = (l + LL - 1) & (LL-1), lp = (l + 1) & (LL-1);
    const float* x0 = x + ((size_t)b*LL + lm)*CIN;
    const float* x1 = x + ((size_t)b*LL + l )*CIN;
    const float* x2 = x + ((size_t)b*LL + lp)*CIN;
    float s = 0.f;
#pragma unroll
    for (int c=0;c<CIN;c++){
        s += x0[c]*__ldg(&Wtok[(0*CIN+c)*DD + d]);
        s += x1[c]*__ldg(&Wtok[(1*CIN+c)*DD + d]);
        s += x2[c]*__ldg(&Wtok[(2*CIN+c)*DD + d]);
    }
    const float* mk = mark + ((size_t)b*LL + l)*MK;
#pragma unroll
    for (int m=0;m<MK;m++) s += mk[m]*__ldg(&Wtem[m*DD + d]);
    out[idx] = s;
    bf16 h,lo; bsplit(s,h,lo); oh[idx]=h; ol[idx]=lo;
}

// ---------------- mean of x_enc over time ----------------
__global__ void meanenc_k(const float* __restrict__ x, float* __restrict__ m){
    __shared__ float red[256];
    int b = blockIdx.x / CIN, c = blockIdx.x % CIN;
    int tid = threadIdx.x;
    float s=0.f;
    for (int l=tid;l<LL;l+=256) s += x[((size_t)b*LL + l)*CIN + c];
    red[tid]=s; __syncthreads();
    for (int o=128;o;o>>=1){ if (tid<o) red[tid]+=red[tid+o]; __syncthreads(); }
    if (tid==0) m[blockIdx.x] = red[0]*(1.0f/1024.0f);
}

__global__ void decinit_k(const float* __restrict__ sx, const float* __restrict__ tx,
                          const float* __restrict__ menc, float* __restrict__ seas,
                          float* __restrict__ trend){
    int idx = blockIdx.x*256 + threadIdx.x;
    if (idx >= BL7) return;
    int c = idx % CIN;
    int l = (idx / CIN) % LL;
    int b = idx / (CIN*LL);
    if (l < 512){
        size_t src = ((size_t)b*LL + 512 + l)*CIN + c;
        seas[idx]  = sx[src];
        trend[idx] = tx[src];
    } else {
        seas[idx]  = 0.f;
        trend[idx] = menc[b*CIN + c];
    }
}

__global__ void trendconv_k(const float* __restrict__ t123, const float* __restrict__ Wt,
                            float* __restrict__ trend){
    int idx = blockIdx.x*256 + threadIdx.x;
    if (idx >= BL7) return;
    int c = idx % CIN;
    int l = (idx / CIN) % LL;
    int b = idx / (CIN*LL);
    int lm = (l + LL - 1) & (LL-1), lp = (l + 1) & (LL-1);
    const float* r0 = t123 + ((size_t)b*LL + lm)*DD;
    const float* r1 = t123 + ((size_t)b*LL + l )*DD;
    const float* r2 = t123 + ((size_t)b*LL + lp)*DD;
    float s = 0.f;
    for (int d=0; d<DD; d++){
        s += r0[d]*__ldg(&Wt[(0*DD+d)*CIN + c]);
        s += r1[d]*__ldg(&Wt[(1*DD+d)*CIN + c]);
        s += r2[d]*__ldg(&Wt[(2*DD+d)*CIN + c]);
    }
    trend[idx] += s;
}

__global__ void final_k(const float* __restrict__ dec, const float* __restrict__ projW,
                        const float* __restrict__ projb, const float* __restrict__ trend,
                        float* __restrict__ out){
    int idx = blockIdx.x*256 + threadIdx.x;
    if (idx >= BB*512*CIN) return;
    int c = idx % CIN;
    int lp = (idx / CIN) % 512;
    int b = idx / (512*CIN);
    int l = 512 + lp;
    const float* r = dec + ((size_t)b*LL + l)*DD;
    float s = projb[c];
    for (int d=0; d<DD; d++) s += r[d]*__ldg(&projW[d*CIN + c]);
    out[idx] = trend[((size_t)b*LL + l)*CIN + c] + s;
}

// ---------------- host orchestration ----------------
static void gemm_tc(const bf16* ah, const bf16* al, const bf16* bh, const bf16* bl,
                    const float* bias, const float* res,
                    float* C, bf16* Ch, bf16* Cl, int N, int K, int gelu){
    dim3 g(N/256, MROWS/128);
    gemm_mma_k<<<g, 512, GEMM_SMEM>>>(ah, al, bh, bl, bias, res, C, Ch, Cl, N, K, gelu);
}
static void splitW(const float* W, bf16* oh, bf16* ol, int Kd, int Nd){
    split_tr_k<<<dim3(Nd/32, Kd/32), dim3(32,8)>>>(W, oh, ol, Kd, Nd);
}

static void run_attn(const float* res,
                     const bf16* xqh, const bf16* xql,
                     const bf16* xkvh, const bf16* xkvl,
                     const float* W, const float* bias, float* outb,
                     float* q, float* k, float* v, float* qt, float* kt,
                     float2* Sp, float* wbuf, int* dbuf,
                     bf16* wbh, bf16* wbl, bf16* rh, bf16* rl){
    splitW(W,            wbh, wbl, DD, DD);
    gemm_tc(xqh, xql,  wbh, wbl, bias,        nullptr, q, nullptr, nullptr, DD, DD, 0);
    splitW(W + DD*DD,    wbh, wbl, DD, DD);
    gemm_tc(xkvh, xkvl, wbh, wbl, bias + DD,  nullptr, k, nullptr, nullptr, DD, DD, 0);
    splitW(W + 2*DD*DD,  wbh, wbl, DD, DD);
    gemm_tc(xkvh, xkvl, wbh, wbl, bias + 2*DD, nullptr, v, nullptr, nullptr, DD, DD, 0);
    dim3 tg(32, 16, BB);
    transpose_k<<<tg, dim3(32,8)>>>(q, qt);
    transpose_k<<<tg, dim3(32,8)>>>(k, kt);
    corr_fwd_k<<<dim3(BB*NH, 4), 256>>>(qt, kt, Sp);
    corr_topk_k<<<BB, 256>>>(Sp, wbuf, dbuf);
    roll_split_k<<<BLD/256, 256>>>(v, wbuf, dbuf, rh, rl);
    splitW(W + 3*DD*DD,  wbh, wbl, DD, DD);
    gemm_tc(rh, rl, wbh, wbl, bias + 3*DD, res, outb, nullptr, nullptr, DD, DD, 0);
}

extern "C" void kernel_launch(void* const* d_in, const int* in_sizes, int n_in,
                              void* d_out, int out_size){
    const float* x_enc      = (const float*)d_in[0];
    const float* x_mark_enc = (const float*)d_in[1];
    const float* x_mark_dec = (const float*)d_in[3];
    const float* W_enc_tok  = (const float*)d_in[4];
    const float* W_enc_tem  = (const float*)d_in[5];
    const float* W_dec_tok  = (const float*)d_in[6];
    const float* W_dec_tem  = (const float*)d_in[7];
    const float* enc_attn_W = (const float*)d_in[8];
    const float* enc_attn_b = (const float*)d_in[9];
    const float* enc_ff1    = (const float*)d_in[10];
    const float* enc_ff2    = (const float*)d_in[11];
    const float* enc_ln_w   = (const float*)d_in[12];
    const float* enc_ln_b   = (const float*)d_in[13];
    const float* dec_self_W = (const float*)d_in[14];
    const float* dec_self_b = (const float*)d_in[15];
    const float* dec_cross_W= (const float*)d_in[16];
    const float* dec_cross_b= (const float*)d_in[17];
    const float* dec_ff1    = (const float*)d_in[18];
    const float* dec_ff2    = (const float*)d_in[19];
    const float* dec_trend_W= (const float*)d_in[20];
    const float* dec_ln_w   = (const float*)d_in[21];
    const float* dec_ln_b   = (const float*)d_in[22];
    const float* proj_W     = (const float*)d_in[23];
    const float* proj_b     = (const float*)d_in[24];
    float* out = (float*)d_out;

    cudaFuncSetAttribute(gemm_mma_k, cudaFuncAttributeMaxDynamicSharedMemorySize, GEMM_SMEM);

    void *pA,*pB,*pq,*pk,*pv,*penc,*pt123,*pqt,*pkt,*pSp,*pcm,*pw,*pd;
    void *psx,*ptx,*pseas,*ptrd,*pmenc;
    void *ps1h,*ps1l,*pech,*pecl,*ps2h,*ps2l,*pwbh,*pwbl;
    cudaGetSymbolAddress(&pA, g_A);       cudaGetSymbolAddress(&pB, g_Bf);
    cudaGetSymbolAddress(&pq, g_q);       cudaGetSymbolAddress(&pk, g_k);
    cudaGetSymbolAddress(&pv, g_v);       cudaGetSymbolAddress(&penc, g_enc);
    cudaGetSymbolAddress(&pt123, g_t123);
    cudaGetSymbolAddress(&pqt, g_qt);     cudaGetSymbolAddress(&pkt, g_kt);
    cudaGetSymbolAddress(&pSp, g_Sp);     cudaGetSymbolAddress(&pcm, g_cm);
    cudaGetSymbolAddress(&pw, g_w);       cudaGetSymbolAddress(&pd, g_dly);
    cudaGetSymbolAddress(&psx, g_sx);     cudaGetSymbolAddress(&ptx, g_tx);
    cudaGetSymbolAddress(&pseas, g_seas); cudaGetSymbolAddress(&ptrd, g_trd);
    cudaGetSymbolAddress(&pmenc, g_menc);
    cudaGetSymbolAddress(&ps1h, g_s1h);   cudaGetSymbolAddress(&ps1l, g_s1l);
    cudaGetSymbolAddress(&pech, g_ench);  cudaGetSymbolAddress(&pecl, g_encl);
    cudaGetSymbolAddress(&ps2h, g_s2h);   cudaGetSymbolAddress(&ps2l, g_s2l);
    cudaGetSymbolAddress(&pwbh, g_wbh);   cudaGetSymbolAddress(&pwbl, g_wbl);

    float *A_=(float*)pA, *B_=(float*)pB, *Q=(float*)pq, *K_=(float*)pk, *V=(float*)pv;
    float *ENC=(float*)penc, *T123=(float*)pt123, *QT=(float*)pqt, *KT=(float*)pkt;
    float2 *SP=(float2*)pSp;
    float *CM=(float*)pcm, *WW=(float*)pw; int *DL=(int*)pd;
    float *SX=(float*)psx, *TX=(float*)ptx, *SEAS=(float*)pseas, *TRD=(float*)ptrd, *MENC=(float*)pmenc;
    bf16 *S1H=(bf16*)ps1h, *S1L=(bf16*)ps1l, *ECH=(bf16*)pech, *ECL=(bf16*)pecl;
    bf16 *S2H=(bf16*)ps2h, *S2L=(bf16*)ps2l, *WBH=(bf16*)pwbh, *WBL=(bf16*)pwbl;

    // ---- decoder init tensors (from x_enc) ----
    decomp_k<<<dim3(1,8,BB), 32>>>(x_enc, SX, TX, CIN, 1, nullptr, nullptr);
    meanenc_k<<<BB*CIN, 256>>>(x_enc, MENC);
    decinit_k<<<(BL7+255)/256, 256>>>(SX, TX, MENC, SEAS, TRD);

    // ---- encoder ----
    embed_k<<<BLD/256, 256>>>(x_enc, x_mark_enc, W_enc_tok, W_enc_tem, A_, S1H, S1L);
    for (int l=0; l<2; l++){
        run_attn(A_, S1H, S1L, S1H, S1L,
                 enc_attn_W + (size_t)l*4*DD*DD, enc_attn_b + (size_t)l*4*DD,
                 B_, Q, K_, V, QT, KT, SP, WW, DL, WBH, WBL, S2H, S2L);
        decomp_k<<<dim3(2,8,BB), 256>>>(B_, A_, nullptr, DD, 0, S1H, S1L);
        splitW(enc_ff1 + (size_t)l*DD*DFF, WBH, WBL, DD, DFF);
        gemm_tc(S1H, S1L, WBH, WBL, nullptr, nullptr, nullptr, S2H, S2L, DFF, DD, 1);
        splitW(enc_ff2 + (size_t)l*DFF*DD, WBH, WBL, DFF, DD);
        gemm_tc(S2H, S2L, WBH, WBL, nullptr, A_, B_, nullptr, nullptr, DD, DFF, 0);
        decomp_k<<<dim3(2,8,BB), 256>>>(B_, A_, nullptr, DD, 0, S1H, S1L);
    }
    ln_k<<<MROWS, 256>>>(A_, enc_ln_w, enc_ln_b, B_);
    zero_k<<<(BB*DD+255)/256, 256>>>(CM, BB*DD);
    colsum_k<<<dim3(2,8,BB), 256>>>(B_, CM);
    colsub_k<<<BLD/256, 256>>>(B_, CM, ENC, ECH, ECL);

    // ---- decoder ----
    embed_k<<<BLD/256, 256>>>(SEAS, x_mark_dec, W_dec_tok, W_dec_tem, A_, S1H, S1L);
    run_attn(A_, S1H, S1L, S1H, S1L, dec_self_W, dec_self_b,
             B_, Q, K_, V, QT, KT, SP, WW, DL, WBH, WBL, S2H, S2L);
    decomp_k<<<dim3(2,8,BB), 256>>>(B_, A_, T123, DD, 1, S1H, S1L);
    run_attn(A_, S1H, S1L, ECH, ECL, dec_cross_W, dec_cross_b,
             B_, Q, K_, V, QT, KT, SP, WW, DL, WBH, WBL, S2H, S2L);
    decomp_k<<<dim3(2,8,BB), 256>>>(B_, A_, T123, DD, 2, S1H, S1L);
    splitW(dec_ff1, WBH, WBL, DD, DFF);
    gemm_tc(S1H, S1L, WBH, WBL, nullptr, nullptr, nullptr, S2H, S2L, DFF, DD, 1);
    splitW(dec_ff2, WBH, WBL, DFF, DD);
    gemm_tc(S2H, S2L, WBH, WBL, nullptr, A_, B_, nullptr, nullptr, DD, DFF, 0);
    decomp_k<<<dim3(2,8,BB), 256>>>(B_, A_, T123, DD, 2, S1H, S1L);
    trendconv_k<<<(BL7+255)/256, 256>>>(T123, dec_trend_W, TRD);
    ln_k<<<MROWS, 256>>>(A_, dec_ln_w, dec_ln_b, B_);
    zero_k<<<(BB*DD+255)/256, 256>>>(CM, BB*DD);
    colsum_k<<<dim3(2,8,BB), 256>>>(B_, CM);
    colsub_k<<<BLD/256, 256>>>(B_, CM, A_, nullptr, nullptr);
    final_k<<<(BB*512*CIN+255)/256, 256>>>(A_, proj_W, proj_b, TRD, out);
}

// round 7
// speedup vs baseline: 1.1664x; 1.1664x over previous
#include <cuda_runtime.h>
#include <cuda_bf16.h>
#include <math.h>

// ---------------- constants ----------------
#define BB   32
#define LL   1024
#define DD   512
#define NH   8
#define HE   64
#define DFF  2048
#define CIN  7
#define MK   4
#define MROWS (BB*LL)          // 32768
#define BLD  (BB*LL*DD)        // 16777216
#define BL7  (BB*LL*CIN)       // 229376
#define TOPK 6

typedef __nv_bfloat16 bf16;

// ---------------- device scratch ----------------
__device__ float g_A   [BLD];
__device__ float g_Bf  [BLD];
__device__ float g_v   [BLD];
__device__ float g_enc [BLD];
__device__ float g_t123[BLD];
__device__ float g_qt  [BLD];
__device__ float g_kt  [BLD];
__device__ float2 g_Sp [BB*NH*4*LL];
__device__ float g_cm  [BB*DD];
__device__ float g_w   [BB*8];
__device__ int   g_dly [BB*8];
__device__ float g_sx  [BL7];
__device__ float g_tx  [BL7];
__device__ float g_seas[BL7];
__device__ float g_trd [BL7];
__device__ float g_menc[BB*CIN];
__device__ float g_wvo [DD*DD];
__device__ float g_bvo [DD];
// bf16 split buffers
__device__ bf16 g_s1h[MROWS*DD];
__device__ bf16 g_s1l[MROWS*DD];
__device__ bf16 g_ench[MROWS*DD];
__device__ bf16 g_encl[MROWS*DD];
__device__ bf16 g_s2h[MROWS*DFF];
__device__ bf16 g_s2l[MROWS*DFF];
__device__ bf16 g_wbh[DFF*DD];
__device__ bf16 g_wbl[DFF*DD];

// ---------------- helpers ----------------
__device__ __forceinline__ void bsplit(float x, bf16& h, bf16& l){
    h = __float2bfloat16(x);
    l = __float2bfloat16(x - __bfloat162float(h));
}
__device__ __forceinline__ unsigned su32(const void* p){
    return (unsigned)__cvta_generic_to_shared(p);
}
__device__ __forceinline__ void cpa16(unsigned dst, const void* src){
    asm volatile("cp.async.cg.shared.global [%0], [%1], 16;" :: "r"(dst), "l"(src));
}
__device__ __forceinline__ void cpa_commit(){
    asm volatile("cp.async.commit_group;" ::: "memory");
}
__device__ __forceinline__ void cpa_wait2(){
    asm volatile("cp.async.wait_group 2;" ::: "memory");
}
__device__ __forceinline__ void ldsm4(unsigned* r, unsigned addr){
    asm volatile("ldmatrix.sync.aligned.m8n8.x4.shared.b16 {%0,%1,%2,%3}, [%4];"
        : "=r"(r[0]), "=r"(r[1]), "=r"(r[2]), "=r"(r[3]) : "r"(addr));
}
__device__ __forceinline__ void mma16(float* d, const unsigned* a, unsigned b0, unsigned b1){
    asm volatile("mma.sync.aligned.m16n8k16.row.col.f32.bf16.bf16.f32 "
        "{%0,%1,%2,%3},{%4,%5,%6,%7},{%8,%9},{%0,%1,%2,%3};"
        : "+f"(d[0]), "+f"(d[1]), "+f"(d[2]), "+f"(d[3])
        : "r"(a[0]), "r"(a[1]), "r"(a[2]), "r"(a[3]), "r"(b0), "r"(b1));
}

// ---------------- split-bf16 mma.sync GEMM (R5 config + transposed-output mode) ----------------
// C(M x N) = (Ah+Al)(Bh+Bl)^T; A: MxK bf16 k-major; B: NxK bf16 k-major.
// 128x128 CTA tile, 512 thr (4x4 warps, 32x32 warp tiles), KT=32, 3-stage cp.async.
// If Ct != null: output written transposed as Ct[(b*DD + col)*LL + l] (fp32, +bias).
#define RSTRIDE 80            // bytes per smem row (32 bf16 + 8 pad)
#define AREA    10240         // 128 rows * 80B
#define STAGEB  40960         // Ah|Al|Bh|Bl
#define GEMM_SMEM (3*STAGEB)  // 122880
__global__ void __launch_bounds__(512,1) gemm_mma_k(
    const bf16* __restrict__ Ahp, const bf16* __restrict__ Alp,
    const bf16* __restrict__ Bhp, const bf16* __restrict__ Blp,
    const float* __restrict__ bias, const float* __restrict__ res,
    float* __restrict__ C, bf16* __restrict__ Ch, bf16* __restrict__ Cl,
    float* __restrict__ Ct,
    int N, int K, int dogelu)
{
    extern __shared__ __align__(16) char dsm[];
    const int tid = threadIdx.x;
    const int lane = tid & 31, warp = tid >> 5;
    const int wm = warp >> 2, wn = warp & 3;
    const int bx = blockIdx.x, by = blockIdx.y;
    const int S = K >> 5;
    const unsigned sbase = su32(dsm);

    // producer mapping: 512 thr = 128 rows x 4 16B-chunks
    const int lrow = tid >> 2, lc16 = tid & 3;
    const bf16* gA_h = Ahp + (size_t)(by*128 + lrow)*K;
    const bf16* gA_l = Alp + (size_t)(by*128 + lrow)*K;
    const bf16* gB_h = Bhp + (size_t)(bx*128 + lrow)*K;
    const bf16* gB_l = Blp + (size_t)(bx*128 + lrow)*K;
    const unsigned sdst = lrow*RSTRIDE + lc16*16;

    float acc[2][4][4];
#pragma unroll
    for (int i=0;i<2;i++)
#pragma unroll
        for (int j=0;j<4;j++)
#pragma unroll
            for (int t=0;t<4;t++) acc[i][j][t]=0.f;

#pragma unroll
    for (int p=0;p<3;p++){
        if (p < S){
            unsigned b = sbase + p*STAGEB + sdst;
            int gk = p*32 + lc16*8;
            cpa16(b,            gA_h + gk);
            cpa16(b + AREA,     gA_l + gk);
            cpa16(b + 2*AREA,   gB_h + gk);
            cpa16(b + 3*AREA,   gB_l + gk);
        }
        cpa_commit();
    }

    const unsigned arow = (wm*32 + (lane & 15))*RSTRIDE + (lane >> 4)*16;
    const unsigned brow = (wn*32 + (lane & 15))*RSTRIDE + (lane >> 4)*16;

    for (int s=0; s<S; s++){
        cpa_wait2();
        __syncthreads();
        const unsigned sb = sbase + (s % 3)*STAGEB;
#pragma unroll
        for (int k16=0; k16<2; k16++){
            const unsigned ko = k16*32;
            unsigned ah[8], al[8], bh[8], bl[8];
            ldsm4(ah,   sb + arow + ko);
            ldsm4(ah+4, sb + arow + ko + 16*RSTRIDE);
            ldsm4(al,   sb + AREA + arow + ko);
            ldsm4(al+4, sb + AREA + arow + ko + 16*RSTRIDE);
            ldsm4(bh,   sb + 2*AREA + brow + ko);
            ldsm4(bh+4, sb + 2*AREA + brow + ko + 16*RSTRIDE);
            ldsm4(bl,   sb + 3*AREA + brow + ko);
            ldsm4(bl+4, sb + 3*AREA + brow + ko + 16*RSTRIDE);
#pragma unroll
            for (int mf=0; mf<2; mf++){
#pragma unroll
                for (int nf=0; nf<4; nf++){
                    int g = (nf>>1)*4 + (nf&1);
                    mma16(acc[mf][nf], ah+mf*4, bh[g], bh[g+2]);
                    mma16(acc[mf][nf], ah+mf*4, bl[g], bl[g+2]);
                    mma16(acc[mf][nf], al+mf*4, bh[g], bh[g+2]);
                }
            }
        }
        __syncthreads();
        if (s+3 < S){
            unsigned b = sbase + (s % 3)*STAGEB + sdst;
            int gk = (s+3)*32 + lc16*8;
            cpa16(b,            gA_h + gk);
            cpa16(b + AREA,     gA_l + gk);
            cpa16(b + 2*AREA,   gB_h + gk);
            cpa16(b + 3*AREA,   gB_l + gk);
        }
        cpa_commit();
    }

    if (Ct){
        // transposed output: stage tile in smem then coalesced write along L
        float* st = (float*)dsm;  // [128 cols][129]
#pragma unroll
        for (int mf=0; mf<2; mf++){
#pragma unroll
            for (int nf=0; nf<4; nf++){
                int rl = wm*32 + mf*16 + (lane>>2);
                int cl = wn*32 + nf*8 + ((lane&3)<<1);
                float* d = acc[mf][nf];
#pragma unroll
                for (int h=0; h<2; h++){
                    float b0 = bias ? __ldg(&bias[bx*128 + cl])   : 0.f;
                    float b1 = bias ? __ldg(&bias[bx*128 + cl+1]) : 0.f;
                    st[cl*129 + rl + 8*h]     = d[2*h]   + b0;
                    st[(cl+1)*129 + rl + 8*h] = d[2*h+1] + b1;
                }
            }
        }
        __syncthreads();
        int gr = by*128;
        int b  = gr >> 10;
        int l0 = gr & 1023;
#pragma unroll
        for (int cc=0; cc<8; cc++){
            int col = warp*8 + cc;
            size_t rowoff = ((size_t)b*DD + bx*128 + col)*LL + l0;
#pragma unroll
            for (int i=0;i<4;i++){
                int r = lane + i*32;
                Ct[rowoff + r] = st[col*129 + r];
            }
        }
        return;
    }

    // standard epilogue
#pragma unroll
    for (int mf=0; mf<2; mf++){
#pragma unroll
        for (int nf=0; nf<4; nf++){
            int r0  = by*128 + wm*32 + mf*16 + (lane>>2);
            int col = bx*128 + wn*32 + nf*8 + ((lane&3)<<1);
            float* d = acc[mf][nf];
#pragma unroll
            for (int h=0; h<2; h++){
                int r = r0 + h*8;
                size_t rowoff = (size_t)r * N;
                float2 o = make_float2(d[2*h], d[2*h+1]);
                if (bias){ o.x += __ldg(&bias[col]); o.y += __ldg(&bias[col+1]); }
                if (dogelu){
                    o.x = 0.5f*o.x*(1.0f+erff(o.x*0.7071067811865476f));
                    o.y = 0.5f*o.y*(1.0f+erff(o.y*0.7071067811865476f));
                }
                if (res){
                    float2 rr = *(const float2*)&res[rowoff + col];
                    o.x += rr.x; o.y += rr.y;
                }
                if (Ch){
                    bf16 h0,l0,h1,l1;
                    bsplit(o.x,h0,l0); bsplit(o.y,h1,l1);
                    __nv_bfloat162 hv; hv.x=h0; hv.y=h1;
                    __nv_bfloat162 lv; lv.x=l0; lv.y=l1;
                    *(__nv_bfloat162*)&Ch[rowoff + col] = hv;
                    *(__nv_bfloat162*)&Cl[rowoff + col] = lv;
                } else {
                    *(float2*)&C[rowoff + col] = o;
                }
            }
        }
    }
}

// ---------------- small fp32 512x512 matmul: C = A@B ----------------
__global__ void matmul512_k(const float* __restrict__ A, const float* __restrict__ B,
                            float* __restrict__ C){
    __shared__ float As[32][33], Bs[32][33];
    int i0 = blockIdx.y*32, j0 = blockIdx.x*32;
    int tx = threadIdx.x, ty = threadIdx.y;
    float acc[4] = {0.f,0.f,0.f,0.f};
    for (int k0=0;k0<512;k0+=32){
        for (int r=ty;r<32;r+=8){
            As[r][tx] = A[(size_t)(i0+r)*512 + k0+tx];
            Bs[r][tx] = B[(size_t)(k0+r)*512 + j0+tx];
        }
        __syncthreads();
#pragma unroll
        for (int k=0;k<32;k++){
            float bv = Bs[k][tx];
#pragma unroll
            for (int u=0;u<4;u++) acc[u] += As[ty+8*u][k]*bv;
        }
        __syncthreads();
    }
#pragma unroll
    for (int u=0;u<4;u++) C[(size_t)(i0+ty+8*u)*512 + j0+tx] = acc[u];
}

// ---------------- bias': bvWo[j] = sum_m bv[m]*Wo[m][j] + bo[j] ----------------
__global__ void biasvo_k(const float* __restrict__ bv, const float* __restrict__ Wo,
                         const float* __restrict__ bo, float* __restrict__ out){
    int j = blockIdx.x*256 + threadIdx.x;
    if (j >= 512) return;
    float s = bo[j];
    for (int m=0;m<512;m++) s += bv[m]*Wo[(size_t)m*512 + j];
    out[j] = s;
}

// ---------------- weight split + transpose: W[Kd x Nd] -> out[Nd x Kd] hi/lo ----------------
__global__ void split_tr_k(const float* __restrict__ W, bf16* __restrict__ oh,
                           bf16* __restrict__ ol, int Kd, int Nd){
    __shared__ float t[32][33];
    int n0 = blockIdx.x*32, k0 = blockIdx.y*32;
    int x = threadIdx.x, y = threadIdx.y;
    for (int i=y;i<32;i+=8)
        t[i][x] = W[(size_t)(k0+i)*Nd + n0 + x];
    __syncthreads();
    for (int i=y;i<32;i+=8){
        float v = t[x][i];
        bf16 h,l; bsplit(v,h,l);
        oh[(size_t)(n0+i)*Kd + k0 + x] = h;
        ol[(size_t)(n0+i)*Kd + k0 + x] = l;
    }
}

// ---------------- FFT helpers ----------------
__device__ __forceinline__ float2 cmul(float2 a, float2 b){
    return make_float2(a.x*b.x - a.y*b.y, a.x*b.y + a.y*b.x);
}
__device__ void fft1024(float2* z, const float2* tw, int tid){
#pragma unroll
    for (int s=0;s<10;s++){
        __syncthreads();
        int half = 1 << s;
#pragma unroll
        for (int r=0;r<2;r++){
            int j = tid + r*256;
            int pos = j & (half-1);
            int grp = j >> s;
            int i0 = (grp << (s+1)) + pos;
            int i1 = i0 + half;
            float2 w = tw[pos << (9 - s)];
            float2 a = z[i0], b = z[i1];
            float2 t = cmul(w, b);
            z[i0] = make_float2(a.x+t.x, a.y+t.y);
            z[i1] = make_float2(a.x-t.x, a.y-t.y);
        }
    }
    __syncthreads();
}

#define EPB 16
__global__ void corr_fwd_k(const float* __restrict__ qt, const float* __restrict__ kt,
                           float2* __restrict__ Sp){
    __shared__ float2 z[1024];
    __shared__ float2 acc[1024];
    __shared__ float2 tw[512];
    int bh = blockIdx.x;
    int chunk = blockIdx.y;
    int tid = threadIdx.x;
    for (int j=tid;j<512;j+=256){
        float s,c; sincosf((float)j * (6.283185307179586f/1024.0f), &s, &c);
        tw[j] = make_float2(c, -s);
    }
    for (int f=tid;f<1024;f+=256) acc[f] = make_float2(0.f,0.f);
    for (int ei=0; ei<EPB; ei++){
        int e = chunk*EPB + ei;
        const float* qp = qt + ((size_t)bh*HE + e)*LL;
        const float* kp = kt + ((size_t)bh*HE + e)*LL;
        __syncthreads();
        for (int t=tid;t<1024;t+=256){
            int r = __brev(t) >> 22;
            z[r] = make_float2(qp[t], kp[t]);
        }
        fft1024(z, tw, tid);
        for (int f=tid;f<1024;f+=256){
            float2 Zf = z[f];
            float2 Zm = z[(1024 - f) & 1023];
            float2 Zc = make_float2(Zm.x, -Zm.y);
            float2 Q  = make_float2(0.5f*(Zf.x+Zc.x), 0.5f*(Zf.y+Zc.y));
            float dx = Zf.x - Zc.x, dy = Zf.y - Zc.y;
            float2 Kk = make_float2(0.5f*dy, -0.5f*dx);
            acc[f].x += Q.x*Kk.x + Q.y*Kk.y;
            acc[f].y += Q.y*Kk.x - Q.x*Kk.y;
        }
    }
    __syncthreads();
    float2* dst = Sp + ((size_t)bh*4 + chunk)*LL;
    for (int f=tid;f<1024;f+=256) dst[f] = acc[f];
}

__global__ void corr_topk_k(const float2* __restrict__ Sp, float* __restrict__ wout,
                            int* __restrict__ dout){
    __shared__ float2 z[1024];
    __shared__ float2 tw[512];
    __shared__ float corr[1024];
    __shared__ float rv[256];
    __shared__ int   ri[256];
    __shared__ float wv[TOPK];
    __shared__ int   dv[TOPK];
    int b = blockIdx.x, tid = threadIdx.x;
    for (int j=tid;j<512;j+=256){
        float s,c; sincosf((float)j * (6.283185307179586f/1024.0f), &s, &c);
        tw[j] = make_float2(c, s);
    }
    for (int f=tid;f<1024;f+=256){
        float sx=0.f, sy=0.f;
        const float2* sp = Sp + (size_t)b*32*LL + f;
#pragma unroll
        for (int sl=0;sl<32;sl++){
            float2 v = sp[(size_t)sl*LL];
            sx += v.x; sy += v.y;
        }
        int r = __brev(f) >> 22;
        z[r] = make_float2(sx, sy);
    }
    fft1024(z, tw, tid);
    const float scale = 1.0f / (1024.0f * 512.0f);
    for (int f=tid;f<1024;f+=256) corr[f] = z[f].x * scale;
    __syncthreads();
    for (int it=0; it<TOPK; it++){
        float best = -1e30f; int bi = 1<<30;
        for (int f=tid;f<1024;f+=256){
            float v = corr[f];
            if (v > best || (v == best && f < bi)){ best = v; bi = f; }
        }
        rv[tid]=best; ri[tid]=bi; __syncthreads();
        for (int off=128; off; off>>=1){
            if (tid < off){
                if (rv[tid+off] > rv[tid] || (rv[tid+off]==rv[tid] && ri[tid+off]<ri[tid])){
                    rv[tid]=rv[tid+off]; ri[tid]=ri[tid+off];
                }
            }
            __syncthreads();
        }
        if (tid==0){ wv[it]=rv[0]; dv[it]=ri[0]; corr[ri[0]] = -1e30f; }
        __syncthreads();
    }
    if (tid==0){
        float mx = wv[0];
        float ex[TOPK]; float s=0.f;
        for (int i=0;i<TOPK;i++){ ex[i]=expf(wv[i]-mx); s+=ex[i]; }
        for (int i=0;i<TOPK;i++){ wout[b*8+i]=ex[i]/s; dout[b*8+i]=dv[i]; }
    }
}

// ---------------- roll & weight + residual -> fp32 ----------------
__global__ void roll_res_k(const float* __restrict__ P, const float* __restrict__ w,
                           const int* __restrict__ d, const float* __restrict__ res,
                           float* __restrict__ out){
    int idx = blockIdx.x*256 + threadIdx.x;
    if (idx >= BLD) return;
    int c = idx & (DD-1);
    int t = (idx >> 9) & (LL-1);
    int b = idx >> 19;
    float s = res[idx];
#pragma unroll
    for (int i=0;i<TOPK;i++){
        int   dl = __ldg(&d[b*8+i]);
        float wi = __ldg(&w[b*8+i]);
        int tt = (t + dl) & (LL-1);
        s += wi * __ldg(&P[((size_t)b*LL + tt)*DD + c]);
    }
    out[idx] = s;
}

// ---------------- series decomposition (moving mean k=25) ----------------
__global__ void decomp_k(const float* __restrict__ x, float* __restrict__ seas,
                         float* __restrict__ trend, int C, int mode,
                         bf16* __restrict__ oh, bf16* __restrict__ ol){
    int b = blockIdx.z;
    int c = blockIdx.x*blockDim.x + threadIdx.x;
    if (c >= C) return;
    int l0 = blockIdx.y * 128;
    const float* xb = x + (size_t)b*LL*C + c;
    float sum = 0.f;
    for (int j=l0-12;j<=l0+12;j++){
        int jj = min(max(j,0), LL-1);
        sum += xb[(size_t)jj*C];
    }
    for (int l=l0; l<l0+128; l++){
        float m = sum * (1.0f/25.0f);
        size_t o = (size_t)b*LL*C + (size_t)l*C + c;
        float sv = x[o] - m;
        seas[o] = sv;
        if (oh){ bf16 h,lo; bsplit(sv,h,lo); oh[o]=h; ol[o]=lo; }
        if (mode==1) trend[o] = m;
        else if (mode==2) trend[o] += m;
        int ja = min(l+13, LL-1), jr = max(l-12, 0);
        sum += xb[(size_t)ja*C] - xb[(size_t)jr*C];
    }
}

// ---------------- layernorm over feature dim ----------------
__global__ void ln_k(const float* __restrict__ x, const float* __restrict__ w,
                     const float* __restrict__ bv, float* __restrict__ y){
    __shared__ float red[256];
    int row = blockIdx.x, tid = threadIdx.x;
    const float* xr = x + (size_t)row*DD;
    float v0 = xr[tid], v1 = xr[tid+256];
    red[tid] = v0+v1; __syncthreads();
    for (int o=128;o;o>>=1){ if (tid<o) red[tid]+=red[tid+o]; __syncthreads(); }
    float mu = red[0]*(1.0f/512.0f);
    __syncthreads();
    float d0=v0-mu, d1=v1-mu;
    red[tid] = d0*d0+d1*d1; __syncthreads();
    for (int o=128;o;o>>=1){ if (tid<o) red[tid]+=red[tid+o]; __syncthreads(); }
    float rstd = rsqrtf(red[0]*(1.0f/512.0f) + 1e-5f);
    y[(size_t)row*DD + tid]     = d0*rstd*w[tid]     + bv[tid];
    y[(size_t)row*DD + tid+256] = d1*rstd*w[tid+256] + bv[tid+256];
}

// ---------------- column (time) mean ----------------
__global__ void zero_k(float* p, int n){
    int i = blockIdx.x*blockDim.x + threadIdx.x;
    if (i < n) p[i] = 0.0f;
}
__global__ void colsum_k(const float* __restrict__ x, float* __restrict__ cm){
    int b = blockIdx.z;
    int c = blockIdx.x*256 + threadIdx.x;
    int l0 = blockIdx.y*128;
    float s=0.f;
    for (int l=l0;l<l0+128;l++) s += x[((size_t)b*LL + l)*DD + c];
    atomicAdd(&cm[b*DD + c], s);
}
__global__ void colsub_k(const float* __restrict__ x, const float* __restrict__ cm,
                         float* __restrict__ y, bf16* __restrict__ oh, bf16* __restrict__ ol){
    int idx = blockIdx.x*256 + threadIdx.x;
    if (idx >= BLD) return;
    int c = idx & (DD-1);
    int b = idx >> 19;
    float v = x[idx] - cm[b*DD + c]*(1.0f/1024.0f);
    y[idx] = v;
    if (oh){ bf16 h,l; bsplit(v,h,l); oh[idx]=h; ol[idx]=l; }
}

// ---------------- embedding (weight-register reuse, 8 l per thread) ----------------
__global__ void embed_k(const float* __restrict__ x, const float* __restrict__ mark,
                        const float* __restrict__ Wtok, const float* __restrict__ Wtem,
                        float* __restrict__ out, bf16* __restrict__ oh, bf16* __restrict__ ol){
    int d = blockIdx.x*256 + threadIdx.x;     // 0..511
    int b = blockIdx.z;
    int l0 = blockIdx.y*8;
    float w[21], wt[4];
#pragma unroll
    for (int i=0;i<21;i++) w[i] = __ldg(&Wtok[(size_t)i*DD + d]);
#pragma unroll
    for (int m=0;m<MK;m++) wt[m] = __ldg(&Wtem[(size_t)m*DD + d]);
#pragma unroll
    for (int i=0;i<8;i++){
        int l = l0 + i;
        int lm = (l + LL - 1) & (LL-1), lp = (l + 1) & (LL-1);
        const float* x0 = x + ((size_t)b*LL + lm)*CIN;
        const float* x1 = x + ((size_t)b*LL + l )*CIN;
        const float* x2 = x + ((size_t)b*LL + lp)*CIN;
        float s = 0.f;
#pragma unroll
        for (int c=0;c<CIN;c++){
            s += x0[c]*w[c];
            s += x1[c]*w[7+c];
            s += x2[c]*w[14+c];
        }
        const float* mk = mark + ((size_t)b*LL + l)*MK;
#pragma unroll
        for (int m=0;m<MK;m++) s += mk[m]*wt[m];
        size_t o = ((size_t)b*LL + l)*DD + d;
        out[o] = s;
        bf16 h,lo; bsplit(s,h,lo); oh[o]=h; ol[o]=lo;
    }
}

// ---------------- mean of x_enc over time ----------------
__global__ void meanenc_k(const float* __restrict__ x, float* __restrict__ m){
    __shared__ float red[256];
    int b = blockIdx.x / CIN, c = blockIdx.x % CIN;
    int tid = threadIdx.x;
    float s=0.f;
    for (int l=tid;l<LL;l+=256) s += x[((size_t)b*LL + l)*CIN + c];
    red[tid]=s; __syncthreads();
    for (int o=128;o;o>>=1){ if (tid<o) red[tid]+=red[tid+o]; __syncthreads(); }
    if (tid==0) m[blockIdx.x] = red[0]*(1.0f/1024.0f);
}

__global__ void decinit_k(const float* __restrict__ sx, const float* __restrict__ tx,
                          const float* __restrict__ menc, float* __restrict__ seas,
                          float* __restrict__ trend){
    int idx = blockIdx.x*256 + threadIdx.x;
    if (idx >= BL7) return;
    int c = idx % CIN;
    int l = (idx / CIN) % LL;
    int b = idx / (CIN*LL);
    if (l < 512){
        size_t src = ((size_t)b*LL + 512 + l)*CIN + c;
        seas[idx]  = sx[src];
        trend[idx] = tx[src];
    } else {
        seas[idx]  = 0.f;
        trend[idx] = menc[b*CIN + c];
    }
}

__global__ void trendconv_k(const float* __restrict__ t123, const float* __restrict__ Wt,
                            float* __restrict__ trend){
    int idx = blockIdx.x*256 + threadIdx.x;
    if (idx >= BL7) return;
    int c = idx % CIN;
    int l = (idx / CIN) % LL;
    int b = idx / (CIN*LL);
    int lm = (l + LL - 1) & (LL-1), lp = (l + 1) & (LL-1);
    const float* r0 = t123 + ((size_t)b*LL + lm)*DD;
    const float* r1 = t123 + ((size_t)b*LL + l )*DD;
    const float* r2 = t123 + ((size_t)b*LL + lp)*DD;
    float s = 0.f;
    for (int d=0; d<DD; d++){
        s += r0[d]*__ldg(&Wt[(0*DD+d)*CIN + c]);
        s += r1[d]*__ldg(&Wt[(1*DD+d)*CIN + c]);
        s += r2[d]*__ldg(&Wt[(2*DD+d)*CIN + c]);
    }
    trend[idx] += s;
}

__global__ void final_k(const float* __restrict__ dec, const float* __restrict__ projW,
                        const float* __restrict__ projb, const float* __restrict__ trend,
                        float* __restrict__ out){
    int idx = blockIdx.x*256 + threadIdx.x;
    if (idx >= BB*512*CIN) return;
    int c = idx % CIN;
    int lp = (idx / CIN) % 512;
    int b = idx / (512*CIN);
    int l = 512 + lp;
    const float* r = dec + ((size_t)b*LL + l)*DD;
    float s = projb[c];
    for (int d=0; d<DD; d++) s += r[d]*__ldg(&projW[d*CIN + c]);
    out[idx] = trend[((size_t)b*LL + l)*CIN + c] + s;
}

// ---------------- host orchestration ----------------
static void gemm_tc(const bf16* ah, const bf16* al, const bf16* bh, const bf16* bl,
                    const float* bias, const float* res,
                    float* C, bf16* Ch, bf16* Cl, float* Ct, int N, int K, int gelu){
    dim3 g(N/128, MROWS/128);
    gemm_mma_k<<<g, 512, GEMM_SMEM>>>(ah, al, bh, bl, bias, res, C, Ch, Cl, Ct, N, K, gelu);
}
static void splitW(const float* W, bf16* oh, bf16* ol, int Kd, int Nd){
    split_tr_k<<<dim3(Nd/32, Kd/32), dim3(32,8)>>>(W, oh, ol, Kd, Nd);
}

static void run_attn(const float* res,
                     const bf16* xqh, const bf16* xql,
                     const bf16* xkvh, const bf16* xkvl,
                     const float* W, const float* bias, float* outb,
                     float* Pv, float* qt, float* kt,
                     float2* Sp, float* wbuf, int* dbuf,
                     bf16* wbh, bf16* wbl, float* wvo, float* bvo){
    // Q, K with transposed output
    splitW(W,          wbh, wbl, DD, DD);
    gemm_tc(xqh, xql,  wbh, wbl, bias,      nullptr, nullptr, nullptr, nullptr, qt, DD, DD, 0);
    splitW(W + DD*DD,  wbh, wbl, DD, DD);
    gemm_tc(xkvh, xkvl, wbh, wbl, bias + DD, nullptr, nullptr, nullptr, nullptr, kt, DD, DD, 0);
    // fused V projection: Wvo = Wv @ Wo, bias' = bv@Wo + bo
    matmul512_k<<<dim3(16,16), dim3(32,8)>>>(W + 2*DD*DD, W + 3*DD*DD, wvo);
    biasvo_k<<<2, 256>>>(bias + 2*DD, W + 3*DD*DD, bias + 3*DD, bvo);
    splitW(wvo, wbh, wbl, DD, DD);
    gemm_tc(xkvh, xkvl, wbh, wbl, bvo, nullptr, Pv, nullptr, nullptr, nullptr, DD, DD, 0);
    // autocorrelation
    corr_fwd_k<<<dim3(BB*NH, 4), 256>>>(qt, kt, Sp);
    corr_topk_k<<<BB, 256>>>(Sp, wbuf, dbuf);
    roll_res_k<<<BLD/256, 256>>>(Pv, wbuf, dbuf, res, outb);
}

extern "C" void kernel_launch(void* const* d_in, const int* in_sizes, int n_in,
                              void* d_out, int out_size){
    const float* x_enc      = (const float*)d_in[0];
    const float* x_mark_enc = (const float*)d_in[1];
    const float* x_mark_dec = (const float*)d_in[3];
    const float* W_enc_tok  = (const float*)d_in[4];
    const float* W_enc_tem  = (const float*)d_in[5];
    const float* W_dec_tok  = (const float*)d_in[6];
    const float* W_dec_tem  = (const float*)d_in[7];
    const float* enc_attn_W = (const float*)d_in[8];
    const float* enc_attn_b = (const float*)d_in[9];
    const float* enc_ff1    = (const float*)d_in[10];
    const float* enc_ff2    = (const float*)d_in[11];
    const float* enc_ln_w   = (const float*)d_in[12];
    const float* enc_ln_b   = (const float*)d_in[13];
    const float* dec_self_W = (const float*)d_in[14];
    const float* dec_self_b = (const float*)d_in[15];
    const float* dec_cross_W= (const float*)d_in[16];
    const float* dec_cross_b= (const float*)d_in[17];
    const float* dec_ff1    = (const float*)d_in[18];
    const float* dec_ff2    = (const float*)d_in[19];
    const float* dec_trend_W= (const float*)d_in[20];
    const float* dec_ln_w   = (const float*)d_in[21];
    const float* dec_ln_b   = (const float*)d_in[22];
    const float* proj_W     = (const float*)d_in[23];
    const float* proj_b     = (const float*)d_in[24];
    float* out = (float*)d_out;

    cudaFuncSetAttribute(gemm_mma_k, cudaFuncAttributeMaxDynamicSharedMemorySize, GEMM_SMEM);

    void *pA,*pB,*pv,*penc,*pt123,*pqt,*pkt,*pSp,*pcm,*pw,*pd;
    void *psx,*ptx,*pseas,*ptrd,*pmenc,*pwvo,*pbvo;
    void *ps1h,*ps1l,*pech,*pecl,*ps2h,*ps2l,*pwbh,*pwbl;
    cudaGetSymbolAddress(&pA, g_A);       cudaGetSymbolAddress(&pB, g_Bf);
    cudaGetSymbolAddress(&pv, g_v);       cudaGetSymbolAddress(&penc, g_enc);
    cudaGetSymbolAddress(&pt123, g_t123);
    cudaGetSymbolAddress(&pqt, g_qt);     cudaGetSymbolAddress(&pkt, g_kt);
    cudaGetSymbolAddress(&pSp, g_Sp);     cudaGetSymbolAddress(&pcm, g_cm);
    cudaGetSymbolAddress(&pw, g_w);       cudaGetSymbolAddress(&pd, g_dly);
    cudaGetSymbolAddress(&psx, g_sx);     cudaGetSymbolAddress(&ptx, g_tx);
    cudaGetSymbolAddress(&pseas, g_seas); cudaGetSymbolAddress(&ptrd, g_trd);
    cudaGetSymbolAddress(&pmenc, g_menc);
    cudaGetSymbolAddress(&pwvo, g_wvo);   cudaGetSymbolAddress(&pbvo, g_bvo);
    cudaGetSymbolAddress(&ps1h, g_s1h);   cudaGetSymbolAddress(&ps1l, g_s1l);
    cudaGetSymbolAddress(&pech, g_ench);  cudaGetSymbolAddress(&pecl, g_encl);
    cudaGetSymbolAddress(&ps2h, g_s2h);   cudaGetSymbolAddress(&ps2l, g_s2l);
    cudaGetSymbolAddress(&pwbh, g_wbh);   cudaGetSymbolAddress(&pwbl, g_wbl);

    float *A_=(float*)pA, *B_=(float*)pB, *V=(float*)pv;
    float *ENC=(float*)penc, *T123=(float*)pt123, *QT=(float*)pqt, *KT=(float*)pkt;
    float2 *SP=(float2*)pSp;
    float *CM=(float*)pcm, *WW=(float*)pw; int *DL=(int*)pd;
    float *SX=(float*)psx, *TX=(float*)ptx, *SEAS=(float*)pseas, *TRD=(float*)ptrd, *MENC=(float*)pmenc;
    float *WVO=(float*)pwvo, *BVO=(float*)pbvo;
    bf16 *S1H=(bf16*)ps1h, *S1L=(bf16*)ps1l, *ECH=(bf16*)pech, *ECL=(bf16*)pecl;
    bf16 *S2H=(bf16*)ps2h, *S2L=(bf16*)ps2l, *WBH=(bf16*)pwbh, *WBL=(bf16*)pwbl;

    // ---- decoder init tensors (from x_enc) ----
    decomp_k<<<dim3(1,8,BB), 32>>>(x_enc, SX, TX, CIN, 1, nullptr, nullptr);
    meanenc_k<<<BB*CIN, 256>>>(x_enc, MENC);
    decinit_k<<<(BL7+255)/256, 256>>>(SX, TX, MENC, SEAS, TRD);

    // ---- encoder ----
    embed_k<<<dim3(2, LL/8, BB), 256>>>(x_enc, x_mark_enc, W_enc_tok, W_enc_tem, A_, S1H, S1L);
    for (int l=0; l<2; l++){
        run_attn(A_, S1H, S1L, S1H, S1L,
                 enc_attn_W + (size_t)l*4*DD*DD, enc_attn_b + (size_t)l*4*DD,
                 B_, V, QT, KT, SP, WW, DL, WBH, WBL, WVO, BVO);
        decomp_k<<<dim3(2,8,BB), 256>>>(B_, A_, nullptr, DD, 0, S1H, S1L);
        splitW(enc_ff1 + (size_t)l*DD*DFF, WBH, WBL, DD, DFF);
        gemm_tc(S1H, S1L, WBH, WBL, nullptr, nullptr, nullptr, S2H, S2L, nullptr, DFF, DD, 1);
        splitW(enc_ff2 + (size_t)l*DFF*DD, WBH, WBL, DFF, DD);
        gemm_tc(S2H, S2L, WBH, WBL, nullptr, A_, B_, nullptr, nullptr, nullptr, DD, DFF, 0);
        decomp_k<<<dim3(2,8,BB), 256>>>(B_, A_, nullptr, DD, 0, S1H, S1L);
    }
    ln_k<<<MROWS, 256>>>(A_, enc_ln_w, enc_ln_b, B_);
    zero_k<<<(BB*DD+255)/256, 256>>>(CM, BB*DD);
    colsum_k<<<dim3(2,8,BB), 256>>>(B_, CM);
    colsub_k<<<BLD/256, 256>>>(B_, CM, ENC, ECH, ECL);

    // ---- decoder ----
    embed_k<<<dim3(2, LL/8, BB), 256>>>(SEAS, x_mark_dec, W_dec_tok, W_dec_tem, A_, S1H, S1L);
    run_attn(A_, S1H, S1L, S1H, S1L, dec_self_W, dec_self_b,
             B_, V, QT, KT, SP, WW, DL, WBH, WBL, WVO, BVO);
    decomp_k<<<dim3(2,8,BB), 256>>>(B_, A_, T123, DD, 1, S1H, S1L);
    run_attn(A_, S1H, S1L, ECH, ECL, dec_cross_W, dec_cross_b,
             B_, V, QT, KT, SP, WW, DL, WBH, WBL, WVO, BVO);
    decomp_k<<<dim3(2,8,BB), 256>>>(B_, A_, T123, DD, 2, S1H, S1L);
    splitW(dec_ff1, WBH, WBL, DD, DFF);
    gemm_tc(S1H, S1L, WBH, WBL, nullptr, nullptr, nullptr, S2H, S2L, nullptr, DFF, DD, 1);
    splitW(dec_ff2, WBH, WBL, DFF, DD);
    gemm_tc(S2H, S2L, WBH, WBL, nullptr, A_, B_, nullptr, nullptr, nullptr, DD, DFF, 0);
    decomp_k<<<dim3(2,8,BB), 256>>>(B_, A_, T123, DD, 2, S1H, S1L);
    trendconv_k<<<(BL7+255)/256, 256>>>(T123, dec_trend_W, TRD);
    ln_k<<<MROWS, 256>>>(A_, dec_ln_w, dec_ln_b, B_);
    zero_k<<<(BB*DD+255)/256, 256>>>(CM, BB*DD);
    colsum_k<<<dim3(2,8,BB), 256>>>(B_, CM);
    colsub_k<<<BLD/256, 256>>>(B_, CM, A_, nullptr, nullptr);
    final_k<<<(BB*512*CIN+255)/256, 256>>>(A_, proj_W, proj_b, TRD, out);
}